// round 1
// baseline (speedup 1.0000x reference)
#include <cuda_runtime.h>
#include <cstdint>
#include <math.h>

#define Bb 16
#define Nn 1024
#define Dd 1024
#define Hh 8
#define HDd 128
#define SCALE_F 0.08838834764831845f   // 1/sqrt(128)
#define NEG_F  -1e30f

// ---------------- scratch (no allocation allowed) ----------------
__device__ float g_Q[Bb*Hh*Nn*HDd];   // [B,H,N,HD]
__device__ float g_K[Bb*Hh*Nn*HDd];
__device__ float g_V[Bb*Hh*Nn*HDd];
__device__ float g_O[Bb*Nn*Dd];       // [B,N,D] (heads concatenated)

// ---------------- helpers ----------------
__device__ __forceinline__ uint32_t f2tf(float x) {
    uint32_t r;
    asm("cvt.rna.tf32.f32 %0, %1;" : "=r"(r) : "f"(x));
    return r;
}

__device__ __forceinline__ void mma8(float c[4], const uint32_t a[4], const uint32_t b[2]) {
    asm volatile(
        "mma.sync.aligned.m16n8k8.row.col.f32.tf32.tf32.f32 "
        "{%0,%1,%2,%3}, {%4,%5,%6,%7}, {%8,%9}, {%0,%1,%2,%3};"
        : "+f"(c[0]), "+f"(c[1]), "+f"(c[2]), "+f"(c[3])
        : "r"(a[0]), "r"(a[1]), "r"(a[2]), "r"(a[3]), "r"(b[0]), "r"(b[1]));
}

// ============================================================
// Kernel 1: fused QKV projection.
// grid: (128 m-tiles, 1, 24 = proj*8 + head), block 256.
// C tile = 128 rows x 128 cols (one full head).
// ============================================================
__global__ __launch_bounds__(256) void qkv_gemm(
    const float* __restrict__ x,
    const float* __restrict__ Wq, const float* __restrict__ Wk, const float* __restrict__ Wv,
    const float* __restrict__ bq, const float* __restrict__ bk, const float* __restrict__ bv)
{
    __shared__ uint32_t As[32][132];   // [k][m]
    __shared__ uint32_t Bs[32][132];   // [k][n]

    const int z = blockIdx.z;
    const int p = z >> 3;
    const int h = z & 7;
    const float* W    = (p == 0 ? Wq : (p == 1 ? Wk : Wv)) + (size_t)h * Dd * HDd;
    const float* bias = (p == 0 ? bq : (p == 1 ? bk : bv)) + h * HDd;
    float* Cout       = (p == 0 ? g_Q : (p == 1 ? g_K : g_V));

    const int m0   = blockIdx.x * 128;
    const int t    = threadIdx.x;
    const int lane = t & 31;
    const int warp = t >> 5;
    const int g    = lane >> 2;
    const int tg   = lane & 3;
    const int wm   = warp >> 1;   // 0..3
    const int wn   = warp & 1;    // 0..1

    float acc[2][8][4];
#pragma unroll
    for (int mt = 0; mt < 2; mt++)
#pragma unroll
        for (int nt = 0; nt < 8; nt++)
#pragma unroll
            for (int i = 0; i < 4; i++) acc[mt][nt][i] = 0.f;

    const int ra = t >> 3;            // 0..31
    const int ca = (t & 7) * 4;       // 0..28
    const int rb = t >> 5;            // 0..7
    const int cb = (t & 31) * 4;      // 0..124

    for (int k0 = 0; k0 < Dd; k0 += 32) {
#pragma unroll
        for (int pp = 0; pp < 4; pp++) {
            int r = ra + pp * 32;
            float4 v = *(const float4*)(x + (size_t)(m0 + r) * Dd + k0 + ca);
            As[ca + 0][r] = f2tf(v.x);
            As[ca + 1][r] = f2tf(v.y);
            As[ca + 2][r] = f2tf(v.z);
            As[ca + 3][r] = f2tf(v.w);
        }
#pragma unroll
        for (int pp = 0; pp < 4; pp++) {
            int k = rb + pp * 8;
            float4 v = *(const float4*)(W + (size_t)(k0 + k) * HDd + cb);
            Bs[k][cb + 0] = f2tf(v.x);
            Bs[k][cb + 1] = f2tf(v.y);
            Bs[k][cb + 2] = f2tf(v.z);
            Bs[k][cb + 3] = f2tf(v.w);
        }
        __syncthreads();

#pragma unroll
        for (int kc = 0; kc < 4; kc++) {
            uint32_t a[2][4];
#pragma unroll
            for (int mt = 0; mt < 2; mt++) {
                int rbase = wm * 32 + mt * 16 + g;
                a[mt][0] = As[kc * 8 + tg    ][rbase];
                a[mt][1] = As[kc * 8 + tg    ][rbase + 8];
                a[mt][2] = As[kc * 8 + tg + 4][rbase];
                a[mt][3] = As[kc * 8 + tg + 4][rbase + 8];
            }
            uint32_t bf[8][2];
#pragma unroll
            for (int nt = 0; nt < 8; nt++) {
                int col = wn * 64 + nt * 8 + g;
                bf[nt][0] = Bs[kc * 8 + tg    ][col];
                bf[nt][1] = Bs[kc * 8 + tg + 4][col];
            }
#pragma unroll
            for (int mt = 0; mt < 2; mt++)
#pragma unroll
                for (int nt = 0; nt < 8; nt++)
                    mma8(acc[mt][nt], a[mt], bf[nt]);
        }
        __syncthreads();
    }

    // epilogue -> [B,H,N,HD]
#pragma unroll
    for (int mt = 0; mt < 2; mt++) {
        int r0 = m0 + wm * 32 + mt * 16 + g;
#pragma unroll
        for (int half = 0; half < 2; half++) {
            int r  = r0 + half * 8;
            int bb = r >> 10;
            int n  = r & 1023;
            float* dst = Cout + (((size_t)(bb * Hh + h)) * Nn + n) * HDd;
#pragma unroll
            for (int nt = 0; nt < 8; nt++) {
                int cc = wn * 64 + nt * 8 + 2 * tg;
                float2 v;
                v.x = acc[mt][nt][half * 2 + 0] + bias[cc];
                v.y = acc[mt][nt][half * 2 + 1] + bias[cc + 1];
                *(float2*)(dst + cc) = v;
            }
        }
    }
}

// ============================================================
// Kernel 2: flash attention with padding mask.
// grid: (16 q-tiles, 8 heads, 16 batch), block 256, dyn smem.
// ============================================================
#define ATTN_SMEM_BYTES (3*64*132*4 + 64*68*4 + 3*64*4 + 2*128*4 + 2*64*4)

__global__ __launch_bounds__(256) void attn_kernel(const int* __restrict__ x_mask)
{
    extern __shared__ char smraw[];
    uint32_t* Qs = (uint32_t*)smraw;            // 64*132
    uint32_t* Ks = Qs + 64 * 132;
    uint32_t* Vs = Ks + 64 * 132;
    uint32_t* Ps = Vs + 64 * 132;               // 64*68
    float* m_s     = (float*)(Ps + 64 * 68);
    float* l_s     = m_s + 64;
    float* alpha_s = l_s + 64;
    float* redm    = alpha_s + 64;              // [2][64]
    float* redsum  = redm + 128;                // [2][64]
    int*   qm      = (int*)(redsum + 128);
    int*   km      = qm + 64;

    const int qt = blockIdx.x, h = blockIdx.y, b = blockIdx.z;
    const int t    = threadIdx.x;
    const int lane = t & 31;
    const int warp = t >> 5;
    const int g    = lane >> 2;
    const int tg   = lane & 3;
    const int wm   = warp >> 1;   // 0..3 : rows
    const int wn   = warp & 1;    // 0..1
    const size_t bh = ((size_t)b * Hh + h) * Nn;
    const int q0 = qt * 64;
    const int rA = wm * 16 + g;
    const int rB = rA + 8;

    // load Q tile (tf32-converted)
    {
        int r = t >> 5;
        int c = (t & 31) * 4;
#pragma unroll
        for (int pp = 0; pp < 8; pp++) {
            int rr = r + pp * 8;
            float4 v = *(const float4*)(g_Q + (bh + q0 + rr) * HDd + c);
            Qs[rr * 132 + c + 0] = f2tf(v.x);
            Qs[rr * 132 + c + 1] = f2tf(v.y);
            Qs[rr * 132 + c + 2] = f2tf(v.z);
            Qs[rr * 132 + c + 3] = f2tf(v.w);
        }
    }
    if (t < 64) {
        qm[t]  = x_mask[b * Nn + q0 + t];
        m_s[t] = -INFINITY;
        l_s[t] = 0.f;
    }

    float o[8][4];
#pragma unroll
    for (int nt = 0; nt < 8; nt++)
#pragma unroll
        for (int i = 0; i < 4; i++) o[nt][i] = 0.f;

    for (int kt = 0; kt < 16; kt++) {
        const int k0 = kt * 64;
        __syncthreads();   // protect K/V smem reuse (and Q on first iter)

        {
            int r = t >> 5;
            int c = (t & 31) * 4;
#pragma unroll
            for (int pp = 0; pp < 8; pp++) {
                int rr = r + pp * 8;
                float4 kv = *(const float4*)(g_K + (bh + k0 + rr) * HDd + c);
                Ks[rr * 132 + c + 0] = f2tf(kv.x);
                Ks[rr * 132 + c + 1] = f2tf(kv.y);
                Ks[rr * 132 + c + 2] = f2tf(kv.z);
                Ks[rr * 132 + c + 3] = f2tf(kv.w);
                float4 vv = *(const float4*)(g_V + (bh + k0 + rr) * HDd + c);
                Vs[rr * 132 + c + 0] = f2tf(vv.x);
                Vs[rr * 132 + c + 1] = f2tf(vv.y);
                Vs[rr * 132 + c + 2] = f2tf(vv.z);
                Vs[rr * 132 + c + 3] = f2tf(vv.w);
            }
        }
        if (t < 64) km[t] = x_mask[b * Nn + k0 + t];
        __syncthreads();

        // ---- S = Q K^T (16x32 per warp) ----
        float s[4][4];
#pragma unroll
        for (int nt = 0; nt < 4; nt++)
#pragma unroll
            for (int i = 0; i < 4; i++) s[nt][i] = 0.f;

#pragma unroll
        for (int kc = 0; kc < 16; kc++) {
            uint32_t a[4];
            a[0] = Qs[rA * 132 + kc * 8 + tg];
            a[1] = Qs[rB * 132 + kc * 8 + tg];
            a[2] = Qs[rA * 132 + kc * 8 + tg + 4];
            a[3] = Qs[rB * 132 + kc * 8 + tg + 4];
#pragma unroll
            for (int nt = 0; nt < 4; nt++) {
                int key = wn * 32 + nt * 8 + g;
                uint32_t bb2[2] = { Ks[key * 132 + kc * 8 + tg],
                                    Ks[key * 132 + kc * 8 + tg + 4] };
                mma8(s[nt], a, bb2);
            }
        }

        // ---- mask + scale ----
        const int qmA = qm[rA], qmB = qm[rB];
#pragma unroll
        for (int nt = 0; nt < 4; nt++) {
            int c0 = wn * 32 + nt * 8 + 2 * tg;
            int k0m = km[c0], k1m = km[c0 + 1];
            s[nt][0] = (qmA & k0m) ? s[nt][0] * SCALE_F : NEG_F;
            s[nt][1] = (qmA & k1m) ? s[nt][1] * SCALE_F : NEG_F;
            s[nt][2] = (qmB & k0m) ? s[nt][2] * SCALE_F : NEG_F;
            s[nt][3] = (qmB & k1m) ? s[nt][3] * SCALE_F : NEG_F;
        }

        // ---- row max (tile-local) ----
        float mA = s[0][0], mB = s[0][2];
#pragma unroll
        for (int nt = 0; nt < 4; nt++) {
            mA = fmaxf(mA, fmaxf(s[nt][0], s[nt][1]));
            mB = fmaxf(mB, fmaxf(s[nt][2], s[nt][3]));
        }
        mA = fmaxf(mA, __shfl_xor_sync(0xffffffffu, mA, 1));
        mA = fmaxf(mA, __shfl_xor_sync(0xffffffffu, mA, 2));
        mB = fmaxf(mB, __shfl_xor_sync(0xffffffffu, mB, 1));
        mB = fmaxf(mB, __shfl_xor_sync(0xffffffffu, mB, 2));
        if (tg == 0) { redm[wn * 64 + rA] = mA; redm[wn * 64 + rB] = mB; }
        __syncthreads();

        if (t < 64) {
            float mo = m_s[t];
            float mn = fmaxf(mo, fmaxf(redm[t], redm[64 + t]));
            m_s[t]     = mn;
            alpha_s[t] = __expf(mo - mn);
        }
        __syncthreads();

        // ---- P = exp(S - m), partial sums, stash tf32 P ----
        const float mnA = m_s[rA], mnB = m_s[rB];
        float sumA = 0.f, sumB = 0.f;
#pragma unroll
        for (int nt = 0; nt < 4; nt++) {
            int c0 = wn * 32 + nt * 8 + 2 * tg;
            float p0 = __expf(s[nt][0] - mnA);
            float p1 = __expf(s[nt][1] - mnA);
            float p2 = __expf(s[nt][2] - mnB);
            float p3 = __expf(s[nt][3] - mnB);
            sumA += p0 + p1;
            sumB += p2 + p3;
            Ps[rA * 68 + c0]     = f2tf(p0);
            Ps[rA * 68 + c0 + 1] = f2tf(p1);
            Ps[rB * 68 + c0]     = f2tf(p2);
            Ps[rB * 68 + c0 + 1] = f2tf(p3);
        }
        sumA += __shfl_xor_sync(0xffffffffu, sumA, 1);
        sumA += __shfl_xor_sync(0xffffffffu, sumA, 2);
        sumB += __shfl_xor_sync(0xffffffffu, sumB, 1);
        sumB += __shfl_xor_sync(0xffffffffu, sumB, 2);
        if (tg == 0) { redsum[wn * 64 + rA] = sumA; redsum[wn * 64 + rB] = sumB; }

        // ---- rescale O by alpha ----
        const float aA = alpha_s[rA], aB = alpha_s[rB];
#pragma unroll
        for (int nt = 0; nt < 8; nt++) {
            o[nt][0] *= aA; o[nt][1] *= aA;
            o[nt][2] *= aB; o[nt][3] *= aB;
        }
        __syncthreads();   // Ps + redsum visible

        if (t < 64) l_s[t] = l_s[t] * alpha_s[t] + redsum[t] + redsum[64 + t];

        // ---- O += P V  (16x64 per warp) ----
#pragma unroll
        for (int kc = 0; kc < 8; kc++) {
            uint32_t a[4];
            a[0] = Ps[rA * 68 + kc * 8 + tg];
            a[1] = Ps[rB * 68 + kc * 8 + tg];
            a[2] = Ps[rA * 68 + kc * 8 + tg + 4];
            a[3] = Ps[rB * 68 + kc * 8 + tg + 4];
#pragma unroll
            for (int nt = 0; nt < 8; nt++) {
                int col = wn * 64 + nt * 8 + g;
                uint32_t bb2[2] = { Vs[(kc * 8 + tg) * 132 + col],
                                    Vs[(kc * 8 + tg + 4) * 132 + col] };
                mma8(o[nt], a, bb2);
            }
        }
    }
    __syncthreads();   // final l_s ready

    const float invA = 1.f / l_s[rA];
    const float invB = 1.f / l_s[rB];
    float* dstA = g_O + ((size_t)b * Nn + q0 + rA) * Dd + h * HDd;
    float* dstB = g_O + ((size_t)b * Nn + q0 + rB) * Dd + h * HDd;
#pragma unroll
    for (int nt = 0; nt < 8; nt++) {
        int c0 = wn * 64 + nt * 8 + 2 * tg;
        float2 vA = { o[nt][0] * invA, o[nt][1] * invA };
        float2 vB = { o[nt][2] * invB, o[nt][3] * invB };
        *(float2*)(dstA + c0) = vA;
        *(float2*)(dstB + c0) = vB;
    }
}

// ============================================================
// Kernel 3: output FC: out = O @ Wfc + bfc
// grid: (128 m-tiles, 8 n-tiles), block 256.
// ============================================================
__global__ __launch_bounds__(256) void fc_gemm(
    const float* __restrict__ Wfc, const float* __restrict__ bfc,
    float* __restrict__ out)
{
    __shared__ uint32_t As[32][132];
    __shared__ uint32_t Bs[32][132];

    const int m0 = blockIdx.x * 128;
    const int n0 = blockIdx.y * 128;
    const int t    = threadIdx.x;
    const int lane = t & 31;
    const int warp = t >> 5;
    const int g    = lane >> 2;
    const int tg   = lane & 3;
    const int wm   = warp >> 1;
    const int wn   = warp & 1;

    float acc[2][8][4];
#pragma unroll
    for (int mt = 0; mt < 2; mt++)
#pragma unroll
        for (int nt = 0; nt < 8; nt++)
#pragma unroll
            for (int i = 0; i < 4; i++) acc[mt][nt][i] = 0.f;

    const int ra = t >> 3;
    const int ca = (t & 7) * 4;
    const int rb = t >> 5;
    const int cb = (t & 31) * 4;

    for (int k0 = 0; k0 < Dd; k0 += 32) {
#pragma unroll
        for (int pp = 0; pp < 4; pp++) {
            int r = ra + pp * 32;
            float4 v = *(const float4*)(g_O + (size_t)(m0 + r) * Dd + k0 + ca);
            As[ca + 0][r] = f2tf(v.x);
            As[ca + 1][r] = f2tf(v.y);
            As[ca + 2][r] = f2tf(v.z);
            As[ca + 3][r] = f2tf(v.w);
        }
#pragma unroll
        for (int pp = 0; pp < 4; pp++) {
            int k = rb + pp * 8;
            float4 v = *(const float4*)(Wfc + (size_t)(k0 + k) * Dd + n0 + cb);
            Bs[k][cb + 0] = f2tf(v.x);
            Bs[k][cb + 1] = f2tf(v.y);
            Bs[k][cb + 2] = f2tf(v.z);
            Bs[k][cb + 3] = f2tf(v.w);
        }
        __syncthreads();

#pragma unroll
        for (int kc = 0; kc < 4; kc++) {
            uint32_t a[2][4];
#pragma unroll
            for (int mt = 0; mt < 2; mt++) {
                int rbase = wm * 32 + mt * 16 + g;
                a[mt][0] = As[kc * 8 + tg    ][rbase];
                a[mt][1] = As[kc * 8 + tg    ][rbase + 8];
                a[mt][2] = As[kc * 8 + tg + 4][rbase];
                a[mt][3] = As[kc * 8 + tg + 4][rbase + 8];
            }
            uint32_t bf[8][2];
#pragma unroll
            for (int nt = 0; nt < 8; nt++) {
                int col = wn * 64 + nt * 8 + g;
                bf[nt][0] = Bs[kc * 8 + tg    ][col];
                bf[nt][1] = Bs[kc * 8 + tg + 4][col];
            }
#pragma unroll
            for (int mt = 0; mt < 2; mt++)
#pragma unroll
                for (int nt = 0; nt < 8; nt++)
                    mma8(acc[mt][nt], a[mt], bf[nt]);
        }
        __syncthreads();
    }

#pragma unroll
    for (int mt = 0; mt < 2; mt++) {
        int r0 = m0 + wm * 32 + mt * 16 + g;
#pragma unroll
        for (int half = 0; half < 2; half++) {
            int r = r0 + half * 8;
            float* dst = out + (size_t)r * Dd + n0;
#pragma unroll
            for (int nt = 0; nt < 8; nt++) {
                int cc = wn * 64 + nt * 8 + 2 * tg;
                float2 v;
                v.x = acc[mt][nt][half * 2 + 0] + bfc[n0 + cc];
                v.y = acc[mt][nt][half * 2 + 1] + bfc[n0 + cc + 1];
                *(float2*)(dst + cc) = v;
            }
        }
    }
}

// ============================================================
extern "C" void kernel_launch(void* const* d_in, const int* in_sizes, int n_in,
                              void* d_out, int out_size)
{
    const float* x      = (const float*)d_in[0];
    const int*   x_mask = (const int*)  d_in[1];
    const float* Wq     = (const float*)d_in[2];
    const float* bq     = (const float*)d_in[3];
    const float* Wk     = (const float*)d_in[4];
    const float* bk     = (const float*)d_in[5];
    const float* Wv     = (const float*)d_in[6];
    const float* bv     = (const float*)d_in[7];
    const float* Wfc    = (const float*)d_in[8];
    const float* bfc    = (const float*)d_in[9];
    float* out = (float*)d_out;

    cudaFuncSetAttribute(attn_kernel, cudaFuncAttributeMaxDynamicSharedMemorySize,
                         ATTN_SMEM_BYTES);

    qkv_gemm<<<dim3(128, 1, 24), 256>>>(x, Wq, Wk, Wv, bq, bk, bv);
    attn_kernel<<<dim3(16, 8, 16), 256, ATTN_SMEM_BYTES>>>(x_mask);
    fc_gemm<<<dim3(128, 8, 1), 256>>>(Wfc, bfc, out);
}

// round 2
// speedup vs baseline: 2.4791x; 2.4791x over previous
#include <cuda_runtime.h>
#include <cuda_fp16.h>
#include <cstdint>
#include <math.h>

#define Bb 16
#define Nn 1024
#define Dd 1024
#define Hh 8
#define HDd 128
#define SCALE_F 0.08838834764831845f   // 1/sqrt(128)
#define NEG_F  -1e30f

// ---------------- scratch (no allocation allowed) ----------------
__device__ __half g_Q[Bb*Hh*Nn*HDd];   // [B,H,N,HD] fp16
__device__ __half g_K[Bb*Hh*Nn*HDd];
__device__ __half g_V[Bb*Hh*Nn*HDd];
__device__ float  g_O[Bb*Nn*Dd];       // [B,N,D] fp32

// ---------------- helpers ----------------
__device__ __forceinline__ uint32_t smaddr(const void* p) {
    return (uint32_t)__cvta_generic_to_shared(p);
}

__device__ __forceinline__ void ldsm4(uint32_t& r0, uint32_t& r1, uint32_t& r2, uint32_t& r3, uint32_t a) {
    asm volatile("ldmatrix.sync.aligned.m8n8.x4.shared.b16 {%0,%1,%2,%3}, [%4];"
                 : "=r"(r0), "=r"(r1), "=r"(r2), "=r"(r3) : "r"(a));
}
__device__ __forceinline__ void ldsm4t(uint32_t& r0, uint32_t& r1, uint32_t& r2, uint32_t& r3, uint32_t a) {
    asm volatile("ldmatrix.sync.aligned.m8n8.x4.trans.shared.b16 {%0,%1,%2,%3}, [%4];"
                 : "=r"(r0), "=r"(r1), "=r"(r2), "=r"(r3) : "r"(a));
}

__device__ __forceinline__ void mma16(float c[4], const uint32_t a[4], const uint32_t b[2]) {
    asm volatile(
        "mma.sync.aligned.m16n8k16.row.col.f32.f16.f16.f32 "
        "{%0,%1,%2,%3}, {%4,%5,%6,%7}, {%8,%9}, {%0,%1,%2,%3};"
        : "+f"(c[0]), "+f"(c[1]), "+f"(c[2]), "+f"(c[3])
        : "r"(a[0]), "r"(a[1]), "r"(a[2]), "r"(a[3]), "r"(b[0]), "r"(b[1]));
}

#define CP16(dst_sm, src_g) \
    asm volatile("cp.async.cg.shared.global [%0], [%1], 16;" :: "r"(dst_sm), "l"(src_g))
#define CP_COMMIT() asm volatile("cp.async.commit_group;")
#define CP_WAIT0()  asm volatile("cp.async.wait_group 0;")

// ============================================================
// Kernel 1: fused QKV projection -> fp16 [B,H,N,HD]
// grid (128 m-tiles, 1, 24 = proj*8+head), block 256
// ============================================================
__global__ __launch_bounds__(256) void qkv_gemm(
    const float* __restrict__ x,
    const float* __restrict__ Wq, const float* __restrict__ Wk, const float* __restrict__ Wv,
    const float* __restrict__ bq, const float* __restrict__ bk, const float* __restrict__ bv)
{
    __shared__ __half As[128][40];    // [m][k], k-step 32, pad 8 (80B stride)
    __shared__ __half Bs[32][136];    // [k][n], pad 8 (272B stride)

    const int z = blockIdx.z;
    const int p = z >> 3;
    const int h = z & 7;
    const float* W    = (p == 0 ? Wq : (p == 1 ? Wk : Wv)) + (size_t)h * Dd * HDd;
    const float* bias = (p == 0 ? bq : (p == 1 ? bk : bv)) + h * HDd;
    __half* Cout      = (p == 0 ? g_Q : (p == 1 ? g_K : g_V));

    const int m0   = blockIdx.x * 128;
    const int t    = threadIdx.x;
    const int lane = t & 31;
    const int warp = t >> 5;
    const int g    = lane >> 2;
    const int tg   = lane & 3;
    const int wm   = warp >> 1;
    const int wn   = warp & 1;

    float acc[2][8][4];
#pragma unroll
    for (int mt = 0; mt < 2; mt++)
#pragma unroll
        for (int nt = 0; nt < 8; nt++)
#pragma unroll
            for (int i = 0; i < 4; i++) acc[mt][nt][i] = 0.f;

    const int ra = t >> 3;            // 0..31
    const int ca = (t & 7) * 4;       // 0..28
    const int rb = t >> 5;            // 0..7
    const int cb = (t & 31) * 4;      // 0..124

    for (int k0 = 0; k0 < Dd; k0 += 32) {
#pragma unroll
        for (int pp = 0; pp < 4; pp++) {
            int r = ra + pp * 32;
            float4 v = *(const float4*)(x + (size_t)(m0 + r) * Dd + k0 + ca);
            As[r][ca + 0] = __float2half_rn(v.x);
            As[r][ca + 1] = __float2half_rn(v.y);
            As[r][ca + 2] = __float2half_rn(v.z);
            As[r][ca + 3] = __float2half_rn(v.w);
        }
#pragma unroll
        for (int pp = 0; pp < 4; pp++) {
            int k = rb + pp * 8;
            float4 v = *(const float4*)(W + (size_t)(k0 + k) * HDd + cb);
            Bs[k][cb + 0] = __float2half_rn(v.x);
            Bs[k][cb + 1] = __float2half_rn(v.y);
            Bs[k][cb + 2] = __float2half_rn(v.z);
            Bs[k][cb + 3] = __float2half_rn(v.w);
        }
        __syncthreads();

#pragma unroll
        for (int ks = 0; ks < 2; ks++) {
            int kk = ks * 16;
            uint32_t a[2][4];
#pragma unroll
            for (int mt = 0; mt < 2; mt++)
                ldsm4(a[mt][0], a[mt][1], a[mt][2], a[mt][3],
                      smaddr(&As[wm * 32 + mt * 16 + (lane & 15)][kk + ((lane >> 4) << 3)]));
            uint32_t bf[8][2];
#pragma unroll
            for (int nb = 0; nb < 4; nb++) {
                int n0 = wn * 64 + nb * 16;
                uint32_t r0, r1, r2, r3;
                ldsm4t(r0, r1, r2, r3,
                       smaddr(&Bs[kk + ((lane >> 3) & 1) * 8 + (lane & 7)][n0 + (lane >> 4) * 8]));
                bf[nb * 2][0] = r0; bf[nb * 2][1] = r1;
                bf[nb * 2 + 1][0] = r2; bf[nb * 2 + 1][1] = r3;
            }
#pragma unroll
            for (int mt = 0; mt < 2; mt++)
#pragma unroll
                for (int nt = 0; nt < 8; nt++)
                    mma16(acc[mt][nt], a[mt], bf[nt]);
        }
        __syncthreads();
    }

    // epilogue -> [B,H,N,HD] fp16
#pragma unroll
    for (int mt = 0; mt < 2; mt++) {
#pragma unroll
        for (int half = 0; half < 2; half++) {
            int r  = m0 + wm * 32 + mt * 16 + g + half * 8;
            int bb = r >> 10;
            int n  = r & 1023;
            __half* dst = Cout + (((size_t)(bb * Hh + h)) * Nn + n) * HDd;
#pragma unroll
            for (int nt = 0; nt < 8; nt++) {
                int cc = wn * 64 + nt * 8 + 2 * tg;
                *(half2*)(dst + cc) = __floats2half2_rn(
                    acc[mt][nt][half * 2 + 0] + bias[cc],
                    acc[mt][nt][half * 2 + 1] + bias[cc + 1]);
            }
        }
    }
}

// ============================================================
// Kernel 2: flash attention (fp16 mma + ldmatrix + cp.async)
// grid (16 q-tiles, 8 heads, 16 batch), block 256, dyn smem
// ============================================================
#define ATTN_SMEM_BYTES (3*64*136*2 + 64*72*2 + 3*64*4 + 2*128*4 + 2*64*4)

__global__ __launch_bounds__(256) void attn_kernel(const int* __restrict__ x_mask)
{
    extern __shared__ char smraw[];
    __half* Qs = (__half*)smraw;        // [64][136]
    __half* Ks = Qs + 64 * 136;
    __half* Vs = Ks + 64 * 136;
    __half* Ps = Vs + 64 * 136;         // [64][72]
    float* m_s     = (float*)(Ps + 64 * 72);
    float* l_s     = m_s + 64;
    float* alpha_s = l_s + 64;
    float* redm    = alpha_s + 64;      // [2][64]
    float* redsum  = redm + 128;
    int*   qm      = (int*)(redsum + 128);
    int*   km      = qm + 64;

    const int qt = blockIdx.x, h = blockIdx.y, b = blockIdx.z;
    const int t    = threadIdx.x;
    const int lane = t & 31;
    const int warp = t >> 5;
    const int g    = lane >> 2;
    const int tg   = lane & 3;
    const int wm   = warp >> 1;   // 0..3 : 16-row q tiles
    const int wn   = warp & 1;    // 0..1 : key halves / hd halves
    const size_t bh = ((size_t)b * Hh + h) * Nn;
    const int q0 = qt * 64;
    const int rA = wm * 16 + g;
    const int rB = rA + 8;

    // Q tile via cp.async (raw fp16 copy)
    {
        int r = t >> 4;             // 0..15
        int c = (t & 15) * 8;       // halves
#pragma unroll
        for (int pp = 0; pp < 4; pp++) {
            int rr = r + pp * 16;
            CP16(smaddr(&Qs[rr * 136 + c]), g_Q + (bh + q0 + rr) * HDd + c);
        }
    }
    CP_COMMIT();
    if (t < 64) {
        qm[t]  = x_mask[b * Nn + q0 + t];
        m_s[t] = -INFINITY;
        l_s[t] = 0.f;
    }

    float o[8][4];
#pragma unroll
    for (int nt = 0; nt < 8; nt++)
#pragma unroll
        for (int i = 0; i < 4; i++) o[nt][i] = 0.f;

    for (int kt = 0; kt < 16; kt++) {
        const int k0 = kt * 64;
        __syncthreads();   // Ks/Vs/Ps reuse safe

        {
            int r = t >> 4;
            int c = (t & 15) * 8;
#pragma unroll
            for (int pp = 0; pp < 4; pp++) {
                int rr = r + pp * 16;
                CP16(smaddr(&Ks[rr * 136 + c]), g_K + (bh + k0 + rr) * HDd + c);
                CP16(smaddr(&Vs[rr * 136 + c]), g_V + (bh + k0 + rr) * HDd + c);
            }
        }
        CP_COMMIT();
        if (t < 64) km[t] = x_mask[b * Nn + k0 + t];
        CP_WAIT0();
        __syncthreads();

        // ---- S = Q K^T : 16 q-rows x 32 keys per warp ----
        float s[4][4];
#pragma unroll
        for (int nt = 0; nt < 4; nt++)
#pragma unroll
            for (int i = 0; i < 4; i++) s[nt][i] = 0.f;

#pragma unroll
        for (int ks = 0; ks < 8; ks++) {
            int kk = ks * 16;
            uint32_t a[4];
            ldsm4(a[0], a[1], a[2], a[3],
                  smaddr(&Qs[(wm * 16 + (lane & 15)) * 136 + kk + ((lane >> 4) << 3)]));
            uint32_t bf[4][2];
#pragma unroll
            for (int nb = 0; nb < 2; nb++) {
                int n0 = wn * 32 + nb * 16;
                uint32_t r0, r1, r2, r3;
                ldsm4(r0, r1, r2, r3,
                      smaddr(&Ks[(n0 + ((lane >> 4) << 3) + (lane & 7)) * 136 + kk + ((lane >> 3) & 1) * 8]));
                bf[nb * 2][0] = r0; bf[nb * 2][1] = r1;
                bf[nb * 2 + 1][0] = r2; bf[nb * 2 + 1][1] = r3;
            }
#pragma unroll
            for (int nt = 0; nt < 4; nt++)
                mma16(s[nt], a, bf[nt]);
        }

        // ---- mask + scale ----
        const int qmA = qm[rA], qmB = qm[rB];
#pragma unroll
        for (int nt = 0; nt < 4; nt++) {
            int c0 = wn * 32 + nt * 8 + 2 * tg;
            int k0m = km[c0], k1m = km[c0 + 1];
            s[nt][0] = (qmA & k0m) ? s[nt][0] * SCALE_F : NEG_F;
            s[nt][1] = (qmA & k1m) ? s[nt][1] * SCALE_F : NEG_F;
            s[nt][2] = (qmB & k0m) ? s[nt][2] * SCALE_F : NEG_F;
            s[nt][3] = (qmB & k1m) ? s[nt][3] * SCALE_F : NEG_F;
        }

        // ---- tile-local row max ----
        float mA = s[0][0], mB = s[0][2];
#pragma unroll
        for (int nt = 0; nt < 4; nt++) {
            mA = fmaxf(mA, fmaxf(s[nt][0], s[nt][1]));
            mB = fmaxf(mB, fmaxf(s[nt][2], s[nt][3]));
        }
        mA = fmaxf(mA, __shfl_xor_sync(0xffffffffu, mA, 1));
        mA = fmaxf(mA, __shfl_xor_sync(0xffffffffu, mA, 2));
        mB = fmaxf(mB, __shfl_xor_sync(0xffffffffu, mB, 1));
        mB = fmaxf(mB, __shfl_xor_sync(0xffffffffu, mB, 2));
        if (tg == 0) { redm[wn * 64 + rA] = mA; redm[wn * 64 + rB] = mB; }
        __syncthreads();

        if (t < 64) {
            float mo = m_s[t];
            float mn = fmaxf(mo, fmaxf(redm[t], redm[64 + t]));
            m_s[t]     = mn;
            alpha_s[t] = __expf(mo - mn);
        }
        __syncthreads();

        // ---- P = exp(S-m), stash fp16, partial sums ----
        const float mnA = m_s[rA], mnB = m_s[rB];
        float sumA = 0.f, sumB = 0.f;
#pragma unroll
        for (int nt = 0; nt < 4; nt++) {
            int c0 = wn * 32 + nt * 8 + 2 * tg;
            float p0 = __expf(s[nt][0] - mnA);
            float p1 = __expf(s[nt][1] - mnA);
            float p2 = __expf(s[nt][2] - mnB);
            float p3 = __expf(s[nt][3] - mnB);
            sumA += p0 + p1;
            sumB += p2 + p3;
            *(half2*)&Ps[rA * 72 + c0] = __floats2half2_rn(p0, p1);
            *(half2*)&Ps[rB * 72 + c0] = __floats2half2_rn(p2, p3);
        }
        sumA += __shfl_xor_sync(0xffffffffu, sumA, 1);
        sumA += __shfl_xor_sync(0xffffffffu, sumA, 2);
        sumB += __shfl_xor_sync(0xffffffffu, sumB, 1);
        sumB += __shfl_xor_sync(0xffffffffu, sumB, 2);
        if (tg == 0) { redsum[wn * 64 + rA] = sumA; redsum[wn * 64 + rB] = sumB; }

        // ---- rescale O ----
        const float aA = alpha_s[rA], aB = alpha_s[rB];
#pragma unroll
        for (int nt = 0; nt < 8; nt++) {
            o[nt][0] *= aA; o[nt][1] *= aA;
            o[nt][2] *= aB; o[nt][3] *= aB;
        }
        __syncthreads();   // Ps + redsum visible

        if (t < 64) l_s[t] = l_s[t] * alpha_s[t] + redsum[t] + redsum[64 + t];

        // ---- O += P V : 16 q-rows x 64 hd-cols per warp ----
#pragma unroll
        for (int ks = 0; ks < 4; ks++) {
            int kk = ks * 16;
            uint32_t a[4];
            ldsm4(a[0], a[1], a[2], a[3],
                  smaddr(&Ps[(wm * 16 + (lane & 15)) * 72 + kk + ((lane >> 4) << 3)]));
#pragma unroll
            for (int nb = 0; nb < 4; nb++) {
                int n0 = wn * 64 + nb * 16;
                uint32_t r0, r1, r2, r3;
                ldsm4t(r0, r1, r2, r3,
                       smaddr(&Vs[(kk + ((lane >> 3) & 1) * 8 + (lane & 7)) * 136 + n0 + (lane >> 4) * 8]));
                uint32_t b0[2] = { r0, r1 };
                uint32_t b1[2] = { r2, r3 };
                mma16(o[nb * 2], a, b0);
                mma16(o[nb * 2 + 1], a, b1);
            }
        }
    }
    __syncthreads();   // final l_s

    const float invA = 1.f / l_s[rA];
    const float invB = 1.f / l_s[rB];
    float* dstA = g_O + ((size_t)b * Nn + q0 + rA) * Dd + h * HDd;
    float* dstB = g_O + ((size_t)b * Nn + q0 + rB) * Dd + h * HDd;
#pragma unroll
    for (int nt = 0; nt < 8; nt++) {
        int c0 = wn * 64 + nt * 8 + 2 * tg;
        float2 vA = { o[nt][0] * invA, o[nt][1] * invA };
        float2 vB = { o[nt][2] * invB, o[nt][3] * invB };
        *(float2*)(dstA + c0) = vA;
        *(float2*)(dstB + c0) = vB;
    }
}

// ============================================================
// Kernel 3: out = g_O @ Wfc + bfc
// grid (128 m-tiles, 8 n-tiles), block 256
// ============================================================
__global__ __launch_bounds__(256) void fc_gemm(
    const float* __restrict__ Wfc, const float* __restrict__ bfc,
    float* __restrict__ out)
{
    __shared__ __half As[128][40];
    __shared__ __half Bs[32][136];

    const int m0 = blockIdx.x * 128;
    const int n0 = blockIdx.y * 128;
    const int t    = threadIdx.x;
    const int lane = t & 31;
    const int warp = t >> 5;
    const int g    = lane >> 2;
    const int tg   = lane & 3;
    const int wm   = warp >> 1;
    const int wn   = warp & 1;

    float acc[2][8][4];
#pragma unroll
    for (int mt = 0; mt < 2; mt++)
#pragma unroll
        for (int nt = 0; nt < 8; nt++)
#pragma unroll
            for (int i = 0; i < 4; i++) acc[mt][nt][i] = 0.f;

    const int ra = t >> 3;
    const int ca = (t & 7) * 4;
    const int rb = t >> 5;
    const int cb = (t & 31) * 4;

    for (int k0 = 0; k0 < Dd; k0 += 32) {
#pragma unroll
        for (int pp = 0; pp < 4; pp++) {
            int r = ra + pp * 32;
            float4 v = *(const float4*)(g_O + (size_t)(m0 + r) * Dd + k0 + ca);
            As[r][ca + 0] = __float2half_rn(v.x);
            As[r][ca + 1] = __float2half_rn(v.y);
            As[r][ca + 2] = __float2half_rn(v.z);
            As[r][ca + 3] = __float2half_rn(v.w);
        }
#pragma unroll
        for (int pp = 0; pp < 4; pp++) {
            int k = rb + pp * 8;
            float4 v = *(const float4*)(Wfc + (size_t)(k0 + k) * Dd + n0 + cb);
            Bs[k][cb + 0] = __float2half_rn(v.x);
            Bs[k][cb + 1] = __float2half_rn(v.y);
            Bs[k][cb + 2] = __float2half_rn(v.z);
            Bs[k][cb + 3] = __float2half_rn(v.w);
        }
        __syncthreads();

#pragma unroll
        for (int ks = 0; ks < 2; ks++) {
            int kk = ks * 16;
            uint32_t a[2][4];
#pragma unroll
            for (int mt = 0; mt < 2; mt++)
                ldsm4(a[mt][0], a[mt][1], a[mt][2], a[mt][3],
                      smaddr(&As[wm * 32 + mt * 16 + (lane & 15)][kk + ((lane >> 4) << 3)]));
            uint32_t bf[8][2];
#pragma unroll
            for (int nb = 0; nb < 4; nb++) {
                int nn0 = wn * 64 + nb * 16;
                uint32_t r0, r1, r2, r3;
                ldsm4t(r0, r1, r2, r3,
                       smaddr(&Bs[kk + ((lane >> 3) & 1) * 8 + (lane & 7)][nn0 + (lane >> 4) * 8]));
                bf[nb * 2][0] = r0; bf[nb * 2][1] = r1;
                bf[nb * 2 + 1][0] = r2; bf[nb * 2 + 1][1] = r3;
            }
#pragma unroll
            for (int mt = 0; mt < 2; mt++)
#pragma unroll
                for (int nt = 0; nt < 8; nt++)
                    mma16(acc[mt][nt], a[mt], bf[nt]);
        }
        __syncthreads();
    }

#pragma unroll
    for (int mt = 0; mt < 2; mt++) {
#pragma unroll
        for (int half = 0; half < 2; half++) {
            int r = m0 + wm * 32 + mt * 16 + g + half * 8;
            float* dst = out + (size_t)r * Dd + n0;
#pragma unroll
            for (int nt = 0; nt < 8; nt++) {
                int cc = wn * 64 + nt * 8 + 2 * tg;
                float2 v;
                v.x = acc[mt][nt][half * 2 + 0] + bfc[n0 + cc];
                v.y = acc[mt][nt][half * 2 + 1] + bfc[n0 + cc + 1];
                *(float2*)(dst + cc) = v;
            }
        }
    }
}

// ============================================================
extern "C" void kernel_launch(void* const* d_in, const int* in_sizes, int n_in,
                              void* d_out, int out_size)
{
    const float* x      = (const float*)d_in[0];
    const int*   x_mask = (const int*)  d_in[1];
    const float* Wq     = (const float*)d_in[2];
    const float* bq     = (const float*)d_in[3];
    const float* Wk     = (const float*)d_in[4];
    const float* bk     = (const float*)d_in[5];
    const float* Wv     = (const float*)d_in[6];
    const float* bv     = (const float*)d_in[7];
    const float* Wfc    = (const float*)d_in[8];
    const float* bfc    = (const float*)d_in[9];
    float* out = (float*)d_out;

    cudaFuncSetAttribute(attn_kernel, cudaFuncAttributeMaxDynamicSharedMemorySize,
                         ATTN_SMEM_BYTES);

    qkv_gemm<<<dim3(128, 1, 24), 256>>>(x, Wq, Wk, Wv, bq, bk, bv);
    attn_kernel<<<dim3(16, 8, 16), 256, ATTN_SMEM_BYTES>>>(x_mask);
    fc_gemm<<<dim3(128, 8, 1), 256>>>(Wfc, bfc, out);
}

// round 3
// speedup vs baseline: 3.4058x; 1.3738x over previous
#include <cuda_runtime.h>
#include <cuda_fp16.h>
#include <cstdint>
#include <math.h>

#define Bb 16
#define Nn 1024
#define Dd 1024
#define Hh 8
#define HDd 128
#define SCALE_F 0.08838834764831845f   // 1/sqrt(128)
#define NEG_F  -1e30f

// ---------------- scratch (static; no allocation allowed) ----------------
__device__ __align__(16) __half g_x16 [Bb*Nn*Dd];     // fp16 copy of x
__device__ __align__(16) __half g_Wq16[Hh*Dd*HDd];
__device__ __align__(16) __half g_Wk16[Hh*Dd*HDd];
__device__ __align__(16) __half g_Wv16[Hh*Dd*HDd];
__device__ __align__(16) __half g_Wfc16[Dd*Dd];
__device__ __align__(16) __half g_Q[Bb*Hh*Nn*HDd];    // [B,H,N,HD]
__device__ __align__(16) __half g_K[Bb*Hh*Nn*HDd];
__device__ __align__(16) __half g_V[Bb*Hh*Nn*HDd];
__device__ __align__(16) __half g_O16[Bb*Nn*Dd];      // [B,N,D]

// ---------------- helpers ----------------
__device__ __forceinline__ uint32_t smaddr(const void* p) {
    return (uint32_t)__cvta_generic_to_shared(p);
}
__device__ __forceinline__ void ldsm4(uint32_t& r0, uint32_t& r1, uint32_t& r2, uint32_t& r3, uint32_t a) {
    asm volatile("ldmatrix.sync.aligned.m8n8.x4.shared.b16 {%0,%1,%2,%3}, [%4];"
                 : "=r"(r0), "=r"(r1), "=r"(r2), "=r"(r3) : "r"(a));
}
__device__ __forceinline__ void ldsm4t(uint32_t& r0, uint32_t& r1, uint32_t& r2, uint32_t& r3, uint32_t a) {
    asm volatile("ldmatrix.sync.aligned.m8n8.x4.trans.shared.b16 {%0,%1,%2,%3}, [%4];"
                 : "=r"(r0), "=r"(r1), "=r"(r2), "=r"(r3) : "r"(a));
}
__device__ __forceinline__ void mma16(float c[4], const uint32_t a[4], const uint32_t b[2]) {
    asm volatile(
        "mma.sync.aligned.m16n8k16.row.col.f32.f16.f16.f32 "
        "{%0,%1,%2,%3}, {%4,%5,%6,%7}, {%8,%9}, {%0,%1,%2,%3};"
        : "+f"(c[0]), "+f"(c[1]), "+f"(c[2]), "+f"(c[3])
        : "r"(a[0]), "r"(a[1]), "r"(a[2]), "r"(a[3]), "r"(b[0]), "r"(b[1]));
}
__device__ __forceinline__ uint32_t packh2(float a, float b) {
    __half2 h = __floats2half2_rn(a, b);
    return *(uint32_t*)&h;
}

#define CP16(dst_sm, src_g) \
    asm volatile("cp.async.cg.shared.global [%0], [%1], 16;" :: "r"(dst_sm), "l"(src_g))
#define CP_COMMIT() asm volatile("cp.async.commit_group;")
#define CP_WAIT0()  asm volatile("cp.async.wait_group 0;")
#define CP_WAIT1()  asm volatile("cp.async.wait_group 1;")

// ============================================================
// Kernel 0: convert fp32 inputs to fp16 scratch
// ============================================================
#define CV_X  4194304           // float4 counts
#define CV_W  262144
__global__ __launch_bounds__(256) void convert_all(
    const float* __restrict__ x,  const float* __restrict__ Wq,
    const float* __restrict__ Wk, const float* __restrict__ Wv,
    const float* __restrict__ Wfc)
{
    const int total = CV_X + 4*CV_W;
    for (int i = blockIdx.x * blockDim.x + threadIdx.x; i < total; i += gridDim.x * blockDim.x) {
        const float* src; __half* dst; int off;
        if (i < CV_X)                 { src = x;   dst = g_x16;  off = i; }
        else if (i < CV_X + CV_W)     { src = Wq;  dst = g_Wq16; off = i - CV_X; }
        else if (i < CV_X + 2*CV_W)   { src = Wk;  dst = g_Wk16; off = i - CV_X - CV_W; }
        else if (i < CV_X + 3*CV_W)   { src = Wv;  dst = g_Wv16; off = i - CV_X - 2*CV_W; }
        else                          { src = Wfc; dst = g_Wfc16; off = i - CV_X - 3*CV_W; }
        float4 v = ((const float4*)src)[off];
        uint2 u;
        u.x = packh2(v.x, v.y);
        u.y = packh2(v.z, v.w);
        ((uint2*)dst)[off] = u;
    }
}

// ============================================================
// GEMM smem geometry (shared by qkv & fc): 2-stage, k-depth 64
// ============================================================
#define A_ST 9216     // 128 * 72 halves
#define B_ST 8704     // 64 * 136 halves
#define GEMM_SMEM ((2*(A_ST + B_ST)) * 2)

// ============================================================
// Kernel 1: fused QKV projection (fp16 in, fp16 out)
// grid (128 m-tiles, 1, 24 = proj*8+head), block 256
// ============================================================
__global__ __launch_bounds__(256) void qkv_gemm(
    const float* __restrict__ bq, const float* __restrict__ bk, const float* __restrict__ bv)
{
    extern __shared__ __half sm[];
    __half* As = sm;                // [2][128][72]
    __half* Bs = sm + 2*A_ST;       // [2][64][136]

    const int z = blockIdx.z;
    const int p = z >> 3;
    const int h = z & 7;
    const __half* W   = (p == 0 ? g_Wq16 : (p == 1 ? g_Wk16 : g_Wv16)) + (size_t)h * Dd * HDd;
    const float* bias = (p == 0 ? bq : (p == 1 ? bk : bv)) + h * HDd;
    __half* Cout      = (p == 0 ? g_Q : (p == 1 ? g_K : g_V));

    const int m0   = blockIdx.x * 128;
    const int t    = threadIdx.x;
    const int lane = t & 31;
    const int warp = t >> 5;
    const int g    = lane >> 2;
    const int tg   = lane & 3;
    const int wm   = warp >> 1;
    const int wn   = warp & 1;

    float acc[2][8][4];
#pragma unroll
    for (int mt = 0; mt < 2; mt++)
#pragma unroll
        for (int nt = 0; nt < 8; nt++)
#pragma unroll
            for (int i = 0; i < 4; i++) acc[mt][nt][i] = 0.f;

    // stage loaders
    auto load_stage = [&](int k0, int st) {
        __half* Ad = As + st * A_ST;
        __half* Bd = Bs + st * B_ST;
#pragma unroll
        for (int pp = 0; pp < 4; pp++) {
            int idx = t + pp * 256;
            int r = idx >> 3, c = (idx & 7) * 8;
            CP16(smaddr(Ad + r * 72 + c), g_x16 + (size_t)(m0 + r) * Dd + k0 + c);
        }
#pragma unroll
        for (int pp = 0; pp < 4; pp++) {
            int idx = t + pp * 256;
            int r = idx >> 4, c = (idx & 15) * 8;
            CP16(smaddr(Bd + r * 136 + c), W + (size_t)(k0 + r) * HDd + c);
        }
    };

    load_stage(0, 0);
    CP_COMMIT();

    for (int s = 0; s < 16; s++) {
        int cur = s & 1;
        if (s < 15) { load_stage((s + 1) * 64, cur ^ 1); CP_COMMIT(); CP_WAIT1(); }
        else        { CP_WAIT0(); }
        __syncthreads();

        const __half* Ac = As + cur * A_ST;
        const __half* Bc = Bs + cur * B_ST;
#pragma unroll
        for (int ks = 0; ks < 4; ks++) {
            int kk = ks * 16;
            uint32_t a[2][4];
#pragma unroll
            for (int mt = 0; mt < 2; mt++)
                ldsm4(a[mt][0], a[mt][1], a[mt][2], a[mt][3],
                      smaddr(Ac + (wm * 32 + mt * 16 + (lane & 15)) * 72 + kk + ((lane >> 4) << 3)));
            uint32_t bf[8][2];
#pragma unroll
            for (int nb = 0; nb < 4; nb++) {
                int n0 = wn * 64 + nb * 16;
                uint32_t r0, r1, r2, r3;
                ldsm4t(r0, r1, r2, r3,
                       smaddr(Bc + (kk + ((lane >> 3) & 1) * 8 + (lane & 7)) * 136 + n0 + (lane >> 4) * 8));
                bf[nb * 2][0] = r0; bf[nb * 2][1] = r1;
                bf[nb * 2 + 1][0] = r2; bf[nb * 2 + 1][1] = r3;
            }
#pragma unroll
            for (int mt = 0; mt < 2; mt++)
#pragma unroll
                for (int nt = 0; nt < 8; nt++)
                    mma16(acc[mt][nt], a[mt], bf[nt]);
        }
        __syncthreads();
    }

    // epilogue -> [B,H,N,HD] fp16 (+bias)
#pragma unroll
    for (int mt = 0; mt < 2; mt++) {
#pragma unroll
        for (int half = 0; half < 2; half++) {
            int r  = m0 + wm * 32 + mt * 16 + g + half * 8;
            int bb = r >> 10;
            int n  = r & 1023;
            __half* dst = Cout + (((size_t)(bb * Hh + h)) * Nn + n) * HDd;
#pragma unroll
            for (int nt = 0; nt < 8; nt++) {
                int cc = wn * 64 + nt * 8 + 2 * tg;
                *(half2*)(dst + cc) = __floats2half2_rn(
                    acc[mt][nt][half * 2 + 0] + bias[cc],
                    acc[mt][nt][half * 2 + 1] + bias[cc + 1]);
            }
        }
    }
}

// ============================================================
// Kernel 2: flash attention, warp-private softmax, P in regs
// grid (8 q-tiles, 8 heads, 16 batch), block 256 (8 warps x 16 rows)
// ============================================================
#define Q_SZ  17408            // 128*136 halves
#define KV_ST 8704             // 64*136 halves
#define ATTN_SMEM_BYTES ((Q_SZ + 4*KV_ST)*2 + 2*64*4)

__global__ __launch_bounds__(256) void attn_kernel(const int* __restrict__ x_mask)
{
    extern __shared__ __half sm[];
    __half* Qs = sm;                    // [128][136]
    __half* Ks = sm + Q_SZ;             // [2][64][136]
    __half* Vs = Ks + 2 * KV_ST;        // [2][64][136]
    int*    km = (int*)(Vs + 2 * KV_ST);// [2][64]

    const int qt = blockIdx.x, h = blockIdx.y, b = blockIdx.z;
    const int t    = threadIdx.x;
    const int lane = t & 31;
    const int warp = t >> 5;           // 0..7, owns 16 q-rows
    const int g    = lane >> 2;
    const int tg   = lane & 3;
    const size_t bh = ((size_t)b * Hh + h) * Nn;
    const int q0 = qt * 128;
    const int rA = warp * 16 + g;
    const int rB = rA + 8;

    // Q tile: 128x128 halves, 8 cp.async per thread
#pragma unroll
    for (int pp = 0; pp < 8; pp++) {
        int idx = t + pp * 256;
        int r = idx >> 4, c = (idx & 15) * 8;
        CP16(smaddr(Qs + r * 136 + c), g_Q + (bh + q0 + r) * HDd + c);
    }
    auto load_kv = [&](int kt, int st) {
        int k0 = kt * 64;
        __half* Kd = Ks + st * KV_ST;
        __half* Vd = Vs + st * KV_ST;
#pragma unroll
        for (int pp = 0; pp < 4; pp++) {
            int idx = t + pp * 256;
            int r = idx >> 4, c = (idx & 15) * 8;
            CP16(smaddr(Kd + r * 136 + c), g_K + (bh + k0 + r) * HDd + c);
            CP16(smaddr(Vd + r * 136 + c), g_V + (bh + k0 + r) * HDd + c);
        }
        if (t < 64) km[st * 64 + t] = x_mask[b * Nn + k0 + t];
    };
    load_kv(0, 0);
    CP_COMMIT();

    const int qmA = x_mask[b * Nn + q0 + rA];
    const int qmB = x_mask[b * Nn + q0 + rB];
    float mA = -INFINITY, mB = -INFINITY, lA = 0.f, lB = 0.f;

    float o[16][4];
#pragma unroll
    for (int j = 0; j < 16; j++)
#pragma unroll
        for (int i = 0; i < 4; i++) o[j][i] = 0.f;

    for (int kt = 0; kt < 16; kt++) {
        const int cur = kt & 1;
        if (kt < 15) { load_kv(kt + 1, cur ^ 1); CP_COMMIT(); CP_WAIT1(); }
        else         { CP_WAIT0(); }
        __syncthreads();

        const __half* Kst = Ks + cur * KV_ST;
        const __half* Vst = Vs + cur * KV_ST;
        const int*    kmc = km + cur * 64;

        // ---- S = Q K^T : 16 rows x 64 keys per warp ----
        float s[8][4];
#pragma unroll
        for (int nt = 0; nt < 8; nt++)
#pragma unroll
            for (int i = 0; i < 4; i++) s[nt][i] = 0.f;

#pragma unroll
        for (int ks = 0; ks < 8; ks++) {
            int kk = ks * 16;
            uint32_t a[4];
            ldsm4(a[0], a[1], a[2], a[3],
                  smaddr(Qs + (warp * 16 + (lane & 15)) * 136 + kk + ((lane >> 4) << 3)));
#pragma unroll
            for (int nb = 0; nb < 4; nb++) {
                int n0 = nb * 16;
                uint32_t r0, r1, r2, r3;
                ldsm4(r0, r1, r2, r3,
                      smaddr(Kst + (n0 + ((lane >> 4) << 3) + (lane & 7)) * 136 + kk + ((lane >> 3) & 1) * 8));
                uint32_t b0[2] = { r0, r1 }, b1[2] = { r2, r3 };
                mma16(s[nb * 2], a, b0);
                mma16(s[nb * 2 + 1], a, b1);
            }
        }

        // ---- mask + scale ----
#pragma unroll
        for (int nt = 0; nt < 8; nt++) {
            int c0 = nt * 8 + 2 * tg;
            int k0m = kmc[c0], k1m = kmc[c0 + 1];
            s[nt][0] = (qmA & k0m) ? s[nt][0] * SCALE_F : NEG_F;
            s[nt][1] = (qmA & k1m) ? s[nt][1] * SCALE_F : NEG_F;
            s[nt][2] = (qmB & k0m) ? s[nt][2] * SCALE_F : NEG_F;
            s[nt][3] = (qmB & k1m) ? s[nt][3] * SCALE_F : NEG_F;
        }

        // ---- warp-private row max ----
        float tmA = s[0][0], tmB = s[0][2];
#pragma unroll
        for (int nt = 0; nt < 8; nt++) {
            tmA = fmaxf(tmA, fmaxf(s[nt][0], s[nt][1]));
            tmB = fmaxf(tmB, fmaxf(s[nt][2], s[nt][3]));
        }
        tmA = fmaxf(tmA, __shfl_xor_sync(0xffffffffu, tmA, 1));
        tmA = fmaxf(tmA, __shfl_xor_sync(0xffffffffu, tmA, 2));
        tmB = fmaxf(tmB, __shfl_xor_sync(0xffffffffu, tmB, 1));
        tmB = fmaxf(tmB, __shfl_xor_sync(0xffffffffu, tmB, 2));

        float mnA = fmaxf(mA, tmA), mnB = fmaxf(mB, tmB);
        float alA = __expf(mA - mnA), alB = __expf(mB - mnB);
        mA = mnA; mB = mnB;

        // ---- P = exp(S - m) in regs (fp16), partial sums ----
        uint32_t pA[8], pB[8];
        float sumA = 0.f, sumB = 0.f;
#pragma unroll
        for (int nt = 0; nt < 8; nt++) {
            float p0 = __expf(s[nt][0] - mnA);
            float p1 = __expf(s[nt][1] - mnA);
            float p2 = __expf(s[nt][2] - mnB);
            float p3 = __expf(s[nt][3] - mnB);
            sumA += p0 + p1;
            sumB += p2 + p3;
            pA[nt] = packh2(p0, p1);
            pB[nt] = packh2(p2, p3);
        }
        sumA += __shfl_xor_sync(0xffffffffu, sumA, 1);
        sumA += __shfl_xor_sync(0xffffffffu, sumA, 2);
        sumB += __shfl_xor_sync(0xffffffffu, sumB, 1);
        sumB += __shfl_xor_sync(0xffffffffu, sumB, 2);
        lA = lA * alA + sumA;
        lB = lB * alB + sumB;

        // ---- rescale O ----
#pragma unroll
        for (int j = 0; j < 16; j++) {
            o[j][0] *= alA; o[j][1] *= alA;
            o[j][2] *= alB; o[j][3] *= alB;
        }

        // ---- O += P V : full 128 hd cols per warp ----
#pragma unroll
        for (int i = 0; i < 4; i++) {
            uint32_t a[4] = { pA[2 * i], pB[2 * i], pA[2 * i + 1], pB[2 * i + 1] };
#pragma unroll
            for (int nb = 0; nb < 8; nb++) {
                int n0 = nb * 16;
                uint32_t r0, r1, r2, r3;
                ldsm4t(r0, r1, r2, r3,
                       smaddr(Vst + (i * 16 + ((lane >> 3) & 1) * 8 + (lane & 7)) * 136 + n0 + (lane >> 4) * 8));
                uint32_t b0[2] = { r0, r1 }, b1[2] = { r2, r3 };
                mma16(o[nb * 2], a, b0);
                mma16(o[nb * 2 + 1], a, b1);
            }
        }
        __syncthreads();
    }

    const float invA = 1.f / lA;
    const float invB = 1.f / lB;
    __half* dA = g_O16 + ((size_t)(b * Nn) + q0 + rA) * Dd + h * HDd;
    __half* dB = g_O16 + ((size_t)(b * Nn) + q0 + rB) * Dd + h * HDd;
#pragma unroll
    for (int j = 0; j < 16; j++) {
        int c0 = j * 8 + 2 * tg;
        *(half2*)(dA + c0) = __floats2half2_rn(o[j][0] * invA, o[j][1] * invA);
        *(half2*)(dB + c0) = __floats2half2_rn(o[j][2] * invB, o[j][3] * invB);
    }
}

// ============================================================
// Kernel 3: out = O16 @ Wfc16 + bfc (fp32 out)
// grid (128 m-tiles, 8 n-tiles), block 256
// ============================================================
__global__ __launch_bounds__(256) void fc_gemm(
    const float* __restrict__ bfc, float* __restrict__ out)
{
    extern __shared__ __half sm[];
    __half* As = sm;
    __half* Bs = sm + 2*A_ST;

    const int m0 = blockIdx.x * 128;
    const int n0 = blockIdx.y * 128;
    const int t    = threadIdx.x;
    const int lane = t & 31;
    const int warp = t >> 5;
    const int g    = lane >> 2;
    const int tg   = lane & 3;
    const int wm   = warp >> 1;
    const int wn   = warp & 1;

    float acc[2][8][4];
#pragma unroll
    for (int mt = 0; mt < 2; mt++)
#pragma unroll
        for (int nt = 0; nt < 8; nt++)
#pragma unroll
            for (int i = 0; i < 4; i++) acc[mt][nt][i] = 0.f;

    auto load_stage = [&](int k0, int st) {
        __half* Ad = As + st * A_ST;
        __half* Bd = Bs + st * B_ST;
#pragma unroll
        for (int pp = 0; pp < 4; pp++) {
            int idx = t + pp * 256;
            int r = idx >> 3, c = (idx & 7) * 8;
            CP16(smaddr(Ad + r * 72 + c), g_O16 + (size_t)(m0 + r) * Dd + k0 + c);
        }
#pragma unroll
        for (int pp = 0; pp < 4; pp++) {
            int idx = t + pp * 256;
            int r = idx >> 4, c = (idx & 15) * 8;
            CP16(smaddr(Bd + r * 136 + c), g_Wfc16 + (size_t)(k0 + r) * Dd + n0 + c);
        }
    };

    load_stage(0, 0);
    CP_COMMIT();

    for (int s = 0; s < 16; s++) {
        int cur = s & 1;
        if (s < 15) { load_stage((s + 1) * 64, cur ^ 1); CP_COMMIT(); CP_WAIT1(); }
        else        { CP_WAIT0(); }
        __syncthreads();

        const __half* Ac = As + cur * A_ST;
        const __half* Bc = Bs + cur * B_ST;
#pragma unroll
        for (int ks = 0; ks < 4; ks++) {
            int kk = ks * 16;
            uint32_t a[2][4];
#pragma unroll
            for (int mt = 0; mt < 2; mt++)
                ldsm4(a[mt][0], a[mt][1], a[mt][2], a[mt][3],
                      smaddr(Ac + (wm * 32 + mt * 16 + (lane & 15)) * 72 + kk + ((lane >> 4) << 3)));
            uint32_t bf[8][2];
#pragma unroll
            for (int nb = 0; nb < 4; nb++) {
                int nn0 = wn * 64 + nb * 16;
                uint32_t r0, r1, r2, r3;
                ldsm4t(r0, r1, r2, r3,
                       smaddr(Bc + (kk + ((lane >> 3) & 1) * 8 + (lane & 7)) * 136 + nn0 + (lane >> 4) * 8));
                bf[nb * 2][0] = r0; bf[nb * 2][1] = r1;
                bf[nb * 2 + 1][0] = r2; bf[nb * 2 + 1][1] = r3;
            }
#pragma unroll
            for (int mt = 0; mt < 2; mt++)
#pragma unroll
                for (int nt = 0; nt < 8; nt++)
                    mma16(acc[mt][nt], a[mt], bf[nt]);
        }
        __syncthreads();
    }

#pragma unroll
    for (int mt = 0; mt < 2; mt++) {
#pragma unroll
        for (int half = 0; half < 2; half++) {
            int r = m0 + wm * 32 + mt * 16 + g + half * 8;
            float* dst = out + (size_t)r * Dd + n0;
#pragma unroll
            for (int nt = 0; nt < 8; nt++) {
                int cc = wn * 64 + nt * 8 + 2 * tg;
                float2 v;
                v.x = acc[mt][nt][half * 2 + 0] + bfc[n0 + cc];
                v.y = acc[mt][nt][half * 2 + 1] + bfc[n0 + cc + 1];
                *(float2*)(dst + cc) = v;
            }
        }
    }
}

// ============================================================
extern "C" void kernel_launch(void* const* d_in, const int* in_sizes, int n_in,
                              void* d_out, int out_size)
{
    const float* x      = (const float*)d_in[0];
    const int*   x_mask = (const int*)  d_in[1];
    const float* Wq     = (const float*)d_in[2];
    const float* bq     = (const float*)d_in[3];
    const float* Wk     = (const float*)d_in[4];
    const float* bk     = (const float*)d_in[5];
    const float* Wv     = (const float*)d_in[6];
    const float* bv     = (const float*)d_in[7];
    const float* Wfc    = (const float*)d_in[8];
    const float* bfc    = (const float*)d_in[9];
    float* out = (float*)d_out;

    static bool attr_done = false;
    if (!attr_done) {
        cudaFuncSetAttribute(attn_kernel, cudaFuncAttributeMaxDynamicSharedMemorySize, ATTN_SMEM_BYTES);
        cudaFuncSetAttribute(qkv_gemm,    cudaFuncAttributeMaxDynamicSharedMemorySize, GEMM_SMEM);
        cudaFuncSetAttribute(fc_gemm,     cudaFuncAttributeMaxDynamicSharedMemorySize, GEMM_SMEM);
        attr_done = true;
    }

    convert_all<<<2048, 256>>>(x, Wq, Wk, Wv, Wfc);
    qkv_gemm<<<dim3(128, 1, 24), 256, GEMM_SMEM>>>(bq, bk, bv);
    attn_kernel<<<dim3(8, 8, 16), 256, ATTN_SMEM_BYTES>>>(x_mask);
    fc_gemm<<<dim3(128, 8, 1), 256, GEMM_SMEM>>>(bfc, out);
}